// round 1
// baseline (speedup 1.0000x reference)
#include <cuda_runtime.h>
#include <math.h>

#define N_NODES 50000
#define N_EDGES 800000
#define EMBED_DIM 64
#define N_PROPS 3
#define FDIM 192
#define F3 576
#define NCLS2 100
#define STEP_MIN 2
#define STEP_MAX 6

// ---------------- device scratch (no dynamic allocation allowed) -----------
__device__ float g_h [(size_t)N_NODES * FDIM];   // node state
__device__ float g_m [(size_t)N_NODES * FDIM];   // edge messages (per node)
__device__ float g_a [(size_t)N_NODES * FDIM];   // aggregated messages
__device__ float g_gi[(size_t)N_NODES * F3];     // input gates
__device__ float g_gh[(size_t)N_NODES * F3];     // hidden gates

// ---------------- embedding gather ----------------
__global__ void embed_gather_kernel(const int* __restrict__ prop_ids,
                                    const float* __restrict__ table) {
    int n = blockIdx.x;
    int f = threadIdx.x;                  // 0..191
    int p = f >> 6;                       // 0..2
    int e = f & 63;
    int id = prop_ids[n * N_PROPS + p];
    g_h[(size_t)n * FDIM + f] = table[(size_t)id * EMBED_DIM + e];
}

// ---------------- zero the aggregation buffer ----------------
__global__ void zero_a_kernel() {
    size_t i = ((size_t)blockIdx.x * blockDim.x + threadIdx.x) * 4;
    if (i < (size_t)N_NODES * FDIM) {
        *reinterpret_cast<float4*>(&g_a[i]) = make_float4(0.f, 0.f, 0.f, 0.f);
    }
}

// ---------------- edge scatter-add: a[dst] += m[src] ----------------
__global__ void scatter_add_kernel(const int* __restrict__ src,
                                   const int* __restrict__ dst) {
    int e = blockIdx.x;
    int f = threadIdx.x;                  // 0..191
    int s = __ldg(&src[e]);
    int d = __ldg(&dst[e]);
    float v = g_m[(size_t)s * FDIM + f];
    atomicAdd(&g_a[(size_t)d * FDIM + f], v);
}

// ---------------- generic fp32 GEMM: C = A(MxK) @ B(NxK)^T + bias ----------
// BM=128, BN=64, BK=16, 256 threads, 8x4 register tile per thread.
#define BM 128
#define BN 64
#define BK 16
#define TM 8
#define TN 4

__global__ __launch_bounds__(256)
void gemm_bt_kernel(const float* __restrict__ A, const float* __restrict__ B,
                    const float* __restrict__ bias, float* __restrict__ C,
                    int M, int N, int K, int ldc, int do_sigmoid) {
    __shared__ float As[BK][BM];
    __shared__ float Bs[BK][BN];

    int tid = threadIdx.x;
    int bm0 = blockIdx.y * BM;
    int bn0 = blockIdx.x * BN;

    int tm = (tid >> 4) * TM;   // 0..120
    int tn = (tid & 15) * TN;   // 0..60

    // A-tile load mapping: 128 rows x 4 float4 per row = 512 float4, 2 per thread
    int a_row = tid >> 1;              // 0..127
    int a_c4  = (tid & 1) * 2;         // 0 or 2
    // B-tile load mapping: 64 rows x 4 float4 per row = 256 float4, 1 per thread
    int b_row = tid >> 2;              // 0..63
    int b_c   = (tid & 3) * 4;         // 0,4,8,12

    float acc[TM][TN];
    #pragma unroll
    for (int i = 0; i < TM; ++i)
        #pragma unroll
        for (int j = 0; j < TN; ++j) acc[i][j] = 0.f;

    for (int k0 = 0; k0 < K; k0 += BK) {
        // load A tile (transposed into smem: As[k][m])
        #pragma unroll
        for (int i = 0; i < 2; ++i) {
            int c = (a_c4 + i) * 4;
            float4 v = make_float4(0.f, 0.f, 0.f, 0.f);
            int gr = bm0 + a_row;
            if (gr < M)
                v = *reinterpret_cast<const float4*>(A + (size_t)gr * K + k0 + c);
            As[c + 0][a_row] = v.x;
            As[c + 1][a_row] = v.y;
            As[c + 2][a_row] = v.z;
            As[c + 3][a_row] = v.w;
        }
        // load B tile (transposed into smem: Bs[k][n])
        {
            float4 v = make_float4(0.f, 0.f, 0.f, 0.f);
            int gn = bn0 + b_row;
            if (gn < N)
                v = *reinterpret_cast<const float4*>(B + (size_t)gn * K + k0 + b_c);
            Bs[b_c + 0][b_row] = v.x;
            Bs[b_c + 1][b_row] = v.y;
            Bs[b_c + 2][b_row] = v.z;
            Bs[b_c + 3][b_row] = v.w;
        }
        __syncthreads();

        #pragma unroll
        for (int k = 0; k < BK; ++k) {
            float ra[TM], rb[TN];
            #pragma unroll
            for (int i = 0; i < TM; ++i) ra[i] = As[k][tm + i];
            #pragma unroll
            for (int j = 0; j < TN; ++j) rb[j] = Bs[k][tn + j];
            #pragma unroll
            for (int i = 0; i < TM; ++i)
                #pragma unroll
                for (int j = 0; j < TN; ++j)
                    acc[i][j] = fmaf(ra[i], rb[j], acc[i][j]);
        }
        __syncthreads();
    }

    #pragma unroll
    for (int i = 0; i < TM; ++i) {
        int gr = bm0 + tm + i;
        if (gr >= M) continue;
        #pragma unroll
        for (int j = 0; j < TN; ++j) {
            int gc = bn0 + tn + j;
            if (gc >= N) continue;
            float v = acc[i][j];
            if (bias) v += bias[gc];
            if (do_sigmoid) v = 1.f / (1.f + expf(-v));
            C[(size_t)gr * ldc + gc] = v;
        }
    }
}

// ---------------- GRU gate fusion: h = (1-z)*n + z*h ----------------
__global__ void gate_kernel() {
    int idx = blockIdx.x * blockDim.x + threadIdx.x;
    if (idx >= N_NODES * FDIM) return;
    int n = idx / FDIM;
    int f = idx - n * FDIM;
    size_t b = (size_t)n * F3 + f;
    float gir = g_gi[b],            ghr = g_gh[b];
    float giz = g_gi[b + FDIM],     ghz = g_gh[b + FDIM];
    float gin = g_gi[b + 2 * FDIM], ghn = g_gh[b + 2 * FDIM];
    float r  = 1.f / (1.f + expf(-(gir + ghr)));
    float z  = 1.f / (1.f + expf(-(giz + ghz)));
    float nn = tanhf(gin + r * ghn);
    size_t hi = (size_t)n * FDIM + f;
    g_h[hi] = (1.f - z) * nn + z * g_h[hi];
}

// ---------------- launch ----------------
static inline dim3 gemm_grid(int M, int N) {
    return dim3((N + BN - 1) / BN, (M + BM - 1) / BM);
}

extern "C" void kernel_launch(void* const* d_in, const int* in_sizes, int n_in,
                              void* d_out, int out_size) {
    const int*   prop_ids = (const int*)d_in[0];
    const int*   src      = (const int*)d_in[1];
    const int*   dst      = (const int*)d_in[2];
    const float* embed    = (const float*)d_in[3];
    const float* W_edge   = (const float*)d_in[4];
    const float* W_ih     = (const float*)d_in[5];
    const float* W_hh     = (const float*)d_in[6];
    const float* b_ih     = (const float*)d_in[7];
    const float* b_hh     = (const float*)d_in[8];
    const float* conv_w   = (const float*)d_in[9];
    const float* conv_b   = (const float*)d_in[10];
    // d_in[11] = step_min (2), d_in[12] = step_max (6) — compile-time constants here
    float* out = (float*)d_out;

    float *h, *m, *a, *gi, *gh;
    cudaGetSymbolAddress((void**)&h,  g_h);
    cudaGetSymbolAddress((void**)&m,  g_m);
    cudaGetSymbolAddress((void**)&a,  g_a);
    cudaGetSymbolAddress((void**)&gi, g_gi);
    cudaGetSymbolAddress((void**)&gh, g_gh);

    // 1) feature init: h = embed_table[prop_ids].reshape(N, F)
    embed_gather_kernel<<<N_NODES, FDIM>>>(prop_ids, embed);

    const int zero_grid = ((N_NODES * FDIM / 4) + 255) / 256;
    const int gate_grid = (N_NODES * FDIM + 255) / 256;

    for (int step = 1; step <= STEP_MAX; ++step) {
        // m = h @ W_edge^T
        gemm_bt_kernel<<<gemm_grid(N_NODES, FDIM), 256>>>(
            h, W_edge, nullptr, m, N_NODES, FDIM, FDIM, FDIM, 0);
        // a = segment_sum(m[src], dst)
        zero_a_kernel<<<zero_grid, 256>>>();
        scatter_add_kernel<<<N_EDGES, FDIM>>>(src, dst);
        // gi = a @ W_ih^T + b_ih ; gh = h @ W_hh^T + b_hh
        gemm_bt_kernel<<<gemm_grid(N_NODES, F3), 256>>>(
            a, W_ih, b_ih, gi, N_NODES, F3, FDIM, F3, 0);
        gemm_bt_kernel<<<gemm_grid(N_NODES, F3), 256>>>(
            h, W_hh, b_hh, gh, N_NODES, F3, FDIM, F3, 0);
        // GRU gates, h updated in place
        gate_kernel<<<gate_grid, 256>>>();
        // logits for steps [STEP_MIN, STEP_MAX]: out[(n*5 + s)*100 + c]
        if (step >= STEP_MIN) {
            int s = step - STEP_MIN;  // 0..4
            gemm_bt_kernel<<<gemm_grid(N_NODES, NCLS2), 256>>>(
                h, conv_w, conv_b, out + s * NCLS2,
                N_NODES, NCLS2, FDIM, (STEP_MAX - STEP_MIN + 1) * NCLS2, 1);
        }
    }
}

// round 3
// speedup vs baseline: 2.8580x; 2.8580x over previous
#include <cuda_runtime.h>
#include <math.h>
#include <stdint.h>

#define N_NODES 50000
#define NP      50048              // padded to 391*128
#define N_EDGES 800000
#define EMBED_DIM 64
#define N_PROPS 3
#define FDIM 192
#define F3 576
#define NCLS2 100
#define STEP_MIN 2
#define STEP_MAX 6

// ---------------- device scratch ----------------
__device__ float g_h [(size_t)NP * FDIM];
__device__ float g_hs[(size_t)NP * FDIM];
__device__ float g_gi[(size_t)NP * F3];
__device__ float g_gh[(size_t)NP * F3];
__device__ float g_wc[(size_t)F3 * FDIM];

// RN-round fp32 -> tf32 bit pattern (low 13 bits zero)
__device__ __forceinline__ float rtf32(float x) {
    uint32_t u = __float_as_uint(x);
    u = (u + 0xfffu + ((u >> 13) & 1u)) & 0xFFFFE000u;
    return __uint_as_float(u);
}

// ================= embedding gather =================
__global__ void embed_gather_kernel(const int* __restrict__ prop_ids,
                                    const float* __restrict__ table) {
    int n = blockIdx.x;
    int f = threadIdx.x;
    int p = f >> 6;
    int e = f & 63;
    int id = prop_ids[n * N_PROPS + p];
    g_h[(size_t)n * FDIM + f] = table[(size_t)id * EMBED_DIM + e];
}

// ================= W_c = W_ih @ W_edge =================
__global__ void fold_kernel(const float* __restrict__ W_ih,
                            const float* __restrict__ W_edge) {
    int i = blockIdx.x;      // 0..575
    int j = threadIdx.x;     // 0..191
    float s = 0.f;
    #pragma unroll 8
    for (int k = 0; k < FDIM; ++k)
        s = fmaf(__ldg(W_ih + i * FDIM + k), __ldg(W_edge + k * FDIM + j), s);
    g_wc[(size_t)i * FDIM + j] = s;
}

// ================= zero hs =================
__global__ void zero_hs_kernel() {
    size_t i = (size_t)blockIdx.x * blockDim.x + threadIdx.x;
    if (i < (size_t)NP * 48)
        reinterpret_cast<float4*>(g_hs)[i] = make_float4(0.f, 0.f, 0.f, 0.f);
}

// ================= scatter: hs[dst] += h[src] (vector red) =================
__global__ __launch_bounds__(192) void scatter_kernel(const int* __restrict__ src,
                                                      const int* __restrict__ dst) {
    int e = blockIdx.x * 4 + threadIdx.x / 48;
    int c = threadIdx.x % 48;
    int s = __ldg(&src[e]);
    int d = __ldg(&dst[e]);
    float4 v = reinterpret_cast<const float4*>(g_h)[(size_t)s * 48 + c];
    float* ap = g_hs + ((size_t)d * 48 + c) * 4;
    asm volatile("red.global.add.v4.f32 [%0], {%1,%2,%3,%4};"
                 :: "l"(ap), "f"(v.x), "f"(v.y), "f"(v.z), "f"(v.w) : "memory");
}

// ================= GRU gate fusion =================
__global__ void gate_kernel() {
    int idx = blockIdx.x * blockDim.x + threadIdx.x;   // float4 index
    if (idx >= N_NODES * 48) return;
    int n = idx / 48;
    int f4 = idx - n * 48;
    const float4* gi = reinterpret_cast<const float4*>(g_gi) + (size_t)n * 144 + f4;
    const float4* gh = reinterpret_cast<const float4*>(g_gh) + (size_t)n * 144 + f4;
    float4 gir = gi[0],  ghr = gh[0];
    float4 giz = gi[48], ghz = gh[48];
    float4 gin = gi[96], ghn = gh[96];
    float4* hp = reinterpret_cast<float4*>(g_h) + (size_t)n * 48 + f4;
    float4 h = *hp, o;
    #define GATE1(X) { \
        float r = 1.f / (1.f + expf(-(gir.X + ghr.X))); \
        float z = 1.f / (1.f + expf(-(giz.X + ghz.X))); \
        float nn = tanhf(gin.X + r * ghn.X); \
        o.X = (1.f - z) * nn + z * h.X; }
    GATE1(x) GATE1(y) GATE1(z) GATE1(w)
    #undef GATE1
    *hp = o;
}

// ================= mma.sync tf32 GEMM =================
// C(M x N) = A(M x 192) @ B(N x 192)^T + bias, optional sigmoid.
// CTA tile 128x64, 8 warps (4x2), warp tile 32x32 (2x4 m16n8k8 atoms).
// BK=32, 6 stages. Smem stride 36 -> conflict-free fragment loads.

#define SA 36

__device__ __forceinline__ void mma_tf32(float* c, const uint32_t* a, const uint32_t* b) {
    asm volatile(
        "mma.sync.aligned.m16n8k8.row.col.f32.tf32.tf32.f32 "
        "{%0,%1,%2,%3}, {%4,%5,%6,%7}, {%8,%9}, {%0,%1,%2,%3};"
        : "+f"(c[0]), "+f"(c[1]), "+f"(c[2]), "+f"(c[3])
        : "r"(a[0]), "r"(a[1]), "r"(a[2]), "r"(a[3]), "r"(b[0]), "r"(b[1]));
}

__global__ __launch_bounds__(256)
void gemm_mma_kernel(const float* __restrict__ A, const float* __restrict__ B,
                     const float* __restrict__ bias, float* __restrict__ C,
                     int Ntot, int Mstore, int ldc, int act) {
    __shared__ float As[128 * SA];
    __shared__ float Bs[64 * SA];

    int tid  = threadIdx.x;
    int lane = tid & 31, wid = tid >> 5;
    int wr = wid & 3, wc2 = wid >> 2;
    int lr = lane >> 2, lc = lane & 3;
    int m0 = blockIdx.y * 128;
    int n0 = blockIdx.x * 64;

    float acc[2][4][4];
    #pragma unroll
    for (int i = 0; i < 2; ++i)
        #pragma unroll
        for (int j = 0; j < 4; ++j)
            #pragma unroll
            for (int q = 0; q < 4; ++q) acc[i][j][q] = 0.f;

    // staging registers for the next K-slab
    float4 ra[4], rb[2];
    int a_row[4], a_c4[4], b_row[2], b_c4[2];
    #pragma unroll
    for (int i = 0; i < 4; ++i) { int it = i * 256 + tid; a_row[i] = it >> 3; a_c4[i] = it & 7; }
    #pragma unroll
    for (int i = 0; i < 2; ++i) { int it = i * 256 + tid; b_row[i] = it >> 3; b_c4[i] = it & 7; }

    #define LOAD_G(k0) { \
        _Pragma("unroll") \
        for (int i = 0; i < 4; ++i) \
            ra[i] = *reinterpret_cast<const float4*>(A + (size_t)(m0 + a_row[i]) * FDIM + (k0) + a_c4[i] * 4); \
        _Pragma("unroll") \
        for (int i = 0; i < 2; ++i) \
            rb[i] = (n0 + b_row[i] < Ntot) \
                ? *reinterpret_cast<const float4*>(B + (size_t)(n0 + b_row[i]) * FDIM + (k0) + b_c4[i] * 4) \
                : make_float4(0.f, 0.f, 0.f, 0.f); \
    }
    #define STORE_S() { \
        _Pragma("unroll") \
        for (int i = 0; i < 4; ++i) { \
            float* p = As + a_row[i] * SA + a_c4[i] * 4; \
            p[0] = rtf32(ra[i].x); p[1] = rtf32(ra[i].y); p[2] = rtf32(ra[i].z); p[3] = rtf32(ra[i].w); \
        } \
        _Pragma("unroll") \
        for (int i = 0; i < 2; ++i) { \
            float* p = Bs + b_row[i] * SA + b_c4[i] * 4; \
            p[0] = rtf32(rb[i].x); p[1] = rtf32(rb[i].y); p[2] = rtf32(rb[i].z); p[3] = rtf32(rb[i].w); \
        } \
    }

    LOAD_G(0);
    STORE_S();
    __syncthreads();

    #pragma unroll 1
    for (int s = 0; s < 6; ++s) {
        if (s < 5) LOAD_G((s + 1) * 32);

        #pragma unroll
        for (int ks = 0; ks < 4; ++ks) {
            int kk = ks * 8 + lc;
            uint32_t a[2][4], b[4][2];
            #pragma unroll
            for (int ma = 0; ma < 2; ++ma) {
                int r = wr * 32 + ma * 16 + lr;
                a[ma][0] = __float_as_uint(As[r * SA + kk]);
                a[ma][1] = __float_as_uint(As[(r + 8) * SA + kk]);
                a[ma][2] = __float_as_uint(As[r * SA + kk + 4]);
                a[ma][3] = __float_as_uint(As[(r + 8) * SA + kk + 4]);
            }
            #pragma unroll
            for (int na = 0; na < 4; ++na) {
                int bn = wc2 * 32 + na * 8 + lr;
                b[na][0] = __float_as_uint(Bs[bn * SA + kk]);
                b[na][1] = __float_as_uint(Bs[bn * SA + kk + 4]);
            }
            #pragma unroll
            for (int ma = 0; ma < 2; ++ma)
                #pragma unroll
                for (int na = 0; na < 4; ++na)
                    mma_tf32(acc[ma][na], a[ma], b[na]);
        }
        __syncthreads();
        if (s < 5) { STORE_S(); __syncthreads(); }
    }

    // ---- epilogue ----
    #pragma unroll
    for (int ma = 0; ma < 2; ++ma) {
        #pragma unroll
        for (int na = 0; na < 4; ++na) {
            int row = m0 + wr * 32 + ma * 16 + lr;
            int col = n0 + wc2 * 32 + na * 8 + lc * 2;
            #pragma unroll
            for (int half = 0; half < 2; ++half) {
                int r = row + half * 8;
                if (r >= Mstore) continue;
                float v0 = acc[ma][na][half * 2 + 0];
                float v1 = acc[ma][na][half * 2 + 1];
                if (col + 1 < Ntot) {
                    v0 += __ldg(bias + col);
                    v1 += __ldg(bias + col + 1);
                    if (act) { v0 = 1.f / (1.f + expf(-v0)); v1 = 1.f / (1.f + expf(-v1)); }
                    *reinterpret_cast<float2*>(C + (size_t)r * ldc + col) = make_float2(v0, v1);
                } else if (col < Ntot) {
                    v0 += __ldg(bias + col);
                    if (act) v0 = 1.f / (1.f + expf(-v0));
                    C[(size_t)r * ldc + col] = v0;
                }
            }
        }
    }
}

// ================= launch =================
extern "C" void kernel_launch(void* const* d_in, const int* in_sizes, int n_in,
                              void* d_out, int out_size) {
    const int*   prop_ids = (const int*)d_in[0];
    const int*   src      = (const int*)d_in[1];
    const int*   dst      = (const int*)d_in[2];
    const float* embed    = (const float*)d_in[3];
    const float* W_edge   = (const float*)d_in[4];
    const float* W_ih     = (const float*)d_in[5];
    const float* W_hh     = (const float*)d_in[6];
    const float* b_ih     = (const float*)d_in[7];
    const float* b_hh     = (const float*)d_in[8];
    const float* conv_w   = (const float*)d_in[9];
    const float* conv_b   = (const float*)d_in[10];
    float* out = (float*)d_out;

    float *h, *hs, *gi, *gh, *wc;
    cudaGetSymbolAddress((void**)&h,  g_h);
    cudaGetSymbolAddress((void**)&hs, g_hs);
    cudaGetSymbolAddress((void**)&gi, g_gi);
    cudaGetSymbolAddress((void**)&gh, g_gh);
    cudaGetSymbolAddress((void**)&wc, g_wc);

    embed_gather_kernel<<<N_NODES, FDIM>>>(prop_ids, embed);
    fold_kernel<<<F3, FDIM>>>(W_ih, W_edge);

    const int MT = NP / 128;                       // 391
    const dim3 grid_576(F3 / 64, MT);              // 9 x 391
    const dim3 grid_100((NCLS2 + 63) / 64, MT);    // 2 x 391
    const int zero_grid = (NP * 48 + 255) / 256;
    const int gate_grid = (N_NODES * 48 + 255) / 256;

    for (int step = 1; step <= STEP_MAX; ++step) {
        zero_hs_kernel<<<zero_grid, 256>>>();
        scatter_kernel<<<N_EDGES / 4, 192>>>(src, dst);
        gemm_mma_kernel<<<grid_576, 256>>>(hs, wc,   b_ih, gi, F3, NP, F3, 0);
        gemm_mma_kernel<<<grid_576, 256>>>(h,  W_hh, b_hh, gh, F3, NP, F3, 0);
        gate_kernel<<<gate_grid, 256>>>();
        if (step >= STEP_MIN) {
            int s = step - STEP_MIN;
            gemm_mma_kernel<<<grid_100, 256>>>(h, conv_w, conv_b, out + s * NCLS2,
                                               NCLS2, N_NODES, 5 * NCLS2, 1);
        }
    }
}

// round 4
// speedup vs baseline: 3.4663x; 1.2129x over previous
#include <cuda_runtime.h>
#include <math.h>
#include <stdint.h>

#define N_NODES 50000
#define NP      50048              // padded to 391*128
#define N_EDGES 800000
#define EMBED_DIM 64
#define N_PROPS 3
#define FDIM 192
#define F3 576
#define NCLS2 100
#define STEP_MIN 2
#define STEP_MAX 6

// ---------------- device scratch ----------------
__device__ float g_h [(size_t)NP * FDIM];
__device__ float g_hs[(size_t)NP * FDIM];
__device__ float g_gi[(size_t)NP * F3];
__device__ float g_gh[(size_t)NP * F3];
__device__ float g_wc[(size_t)F3 * FDIM];
__device__ int   g_deg[NP];
__device__ int   g_rowp[NP + 1];
__device__ int   g_cursor[NP];
__device__ int   g_csr[N_EDGES];

// RN-round fp32 -> tf32 bit pattern (low 13 bits zero)
__device__ __forceinline__ float rtf32(float x) {
    uint32_t u = __float_as_uint(x);
    u = (u + 0xfffu + ((u >> 13) & 1u)) & 0xFFFFE000u;
    return __uint_as_float(u);
}

// ================= embedding gather =================
__global__ void embed_gather_kernel(const int* __restrict__ prop_ids,
                                    const float* __restrict__ table) {
    int n = blockIdx.x;
    int f = threadIdx.x;
    int p = f >> 6;
    int e = f & 63;
    int id = prop_ids[n * N_PROPS + p];
    g_h[(size_t)n * FDIM + f] = table[(size_t)id * EMBED_DIM + e];
}

// ================= W_c = W_ih @ W_edge =================
__global__ void fold_kernel(const float* __restrict__ W_ih,
                            const float* __restrict__ W_edge) {
    int i = blockIdx.x;
    int j = threadIdx.x;
    float s = 0.f;
    #pragma unroll 8
    for (int k = 0; k < FDIM; ++k)
        s = fmaf(__ldg(W_ih + i * FDIM + k), __ldg(W_edge + k * FDIM + j), s);
    g_wc[(size_t)i * FDIM + j] = s;
}

// ================= CSR build =================
__global__ void zero_deg_kernel() {
    int i = blockIdx.x * 256 + threadIdx.x;
    if (i < NP) g_deg[i] = 0;
}
__global__ void csr_count_kernel(const int* __restrict__ dst) {
    int e = blockIdx.x * 256 + threadIdx.x;
    if (e < N_EDGES) atomicAdd(&g_deg[dst[e]], 1);
}
// single-block exclusive scan over g_deg -> g_rowp, g_cursor
__global__ __launch_bounds__(1024) void scan_kernel() {
    __shared__ int part[1024];
    const int CH = 49;                 // 1024*49 >= NP
    int t = threadIdx.x;
    int base = t * CH;
    int s = 0;
    #pragma unroll 7
    for (int i = 0; i < CH; ++i) {
        int idx = base + i;
        if (idx < NP) s += g_deg[idx];
    }
    part[t] = s;
    __syncthreads();
    for (int off = 1; off < 1024; off <<= 1) {
        int v = part[t];
        int u = (t >= off) ? part[t - off] : 0;
        __syncthreads();
        part[t] = v + u;
        __syncthreads();
    }
    int run = (t > 0) ? part[t - 1] : 0;
    for (int i = 0; i < CH; ++i) {
        int idx = base + i;
        if (idx < NP) {
            g_rowp[idx]   = run;
            g_cursor[idx] = run;
            run += g_deg[idx];
        }
    }
    if (t == 0) g_rowp[NP] = N_EDGES;
}
__global__ void csr_fill_kernel(const int* __restrict__ src,
                                const int* __restrict__ dst) {
    int e = blockIdx.x * 256 + threadIdx.x;
    if (e < N_EDGES) {
        int p = atomicAdd(&g_cursor[dst[e]], 1);
        g_csr[p] = src[e];
    }
}

// ================= aggregation: hs[n] = sum_{e: dst=n} h[src[e]] =================
__global__ __launch_bounds__(192) void gather_kernel() {
    int g = threadIdx.x / 48;
    int c = threadIdx.x % 48;
    int n = blockIdx.x * 4 + g;
    int beg = __ldg(&g_rowp[n]);
    int end = __ldg(&g_rowp[n + 1]);
    const float4* h4 = reinterpret_cast<const float4*>(g_h);
    float4 v = make_float4(0.f, 0.f, 0.f, 0.f);
    int i = beg;
    for (; i + 2 <= end; i += 2) {
        int s0 = __ldg(&g_csr[i]);
        int s1 = __ldg(&g_csr[i + 1]);
        float4 a = h4[(size_t)s0 * 48 + c];
        float4 b = h4[(size_t)s1 * 48 + c];
        v.x += a.x + b.x; v.y += a.y + b.y;
        v.z += a.z + b.z; v.w += a.w + b.w;
    }
    if (i < end) {
        int s0 = __ldg(&g_csr[i]);
        float4 a = h4[(size_t)s0 * 48 + c];
        v.x += a.x; v.y += a.y; v.z += a.z; v.w += a.w;
    }
    reinterpret_cast<float4*>(g_hs)[(size_t)n * 48 + c] = v;
}

// ================= GRU gate fusion =================
__global__ void gate_kernel() {
    int idx = blockIdx.x * blockDim.x + threadIdx.x;   // float4 index
    if (idx >= N_NODES * 48) return;
    int n = idx / 48;
    int f4 = idx - n * 48;
    const float4* gi = reinterpret_cast<const float4*>(g_gi) + (size_t)n * 144 + f4;
    const float4* gh = reinterpret_cast<const float4*>(g_gh) + (size_t)n * 144 + f4;
    float4 gir = gi[0],  ghr = gh[0];
    float4 giz = gi[48], ghz = gh[48];
    float4 gin = gi[96], ghn = gh[96];
    float4* hp = reinterpret_cast<float4*>(g_h) + (size_t)n * 48 + f4;
    float4 h = *hp, o;
    #define GATE1(X) { \
        float r = 1.f / (1.f + expf(-(gir.X + ghr.X))); \
        float z = 1.f / (1.f + expf(-(giz.X + ghz.X))); \
        float nn = tanhf(gin.X + r * ghn.X); \
        o.X = (1.f - z) * nn + z * h.X; }
    GATE1(x) GATE1(y) GATE1(z) GATE1(w)
    #undef GATE1
    *hp = o;
}

// ================= mma.sync tf32 GEMM =================
// C(M x N) = A(M x 192) @ B(N x 192)^T + bias, optional sigmoid.
// CTA tile 128x64, 8 warps (4x2), warp tile 32x32 (2x4 m16n8k8 atoms).
// BK=32, 6 slabs, DOUBLE-BUFFERED smem (one sync per slab).

#define SA 36
#define ASZ (128 * SA)
#define BSZ (64 * SA)
#define SMEM_FLOATS (2 * (ASZ + BSZ))

__device__ __forceinline__ void mma_tf32(float* c, const uint32_t* a, const uint32_t* b) {
    asm volatile(
        "mma.sync.aligned.m16n8k8.row.col.f32.tf32.tf32.f32 "
        "{%0,%1,%2,%3}, {%4,%5,%6,%7}, {%8,%9}, {%0,%1,%2,%3};"
        : "+f"(c[0]), "+f"(c[1]), "+f"(c[2]), "+f"(c[3])
        : "r"(a[0]), "r"(a[1]), "r"(a[2]), "r"(a[3]), "r"(b[0]), "r"(b[1]));
}

__global__ __launch_bounds__(256)
void gemm_mma_kernel(const float* __restrict__ A, const float* __restrict__ B,
                     const float* __restrict__ bias, float* __restrict__ C,
                     int Ntot, int Mstore, int ldc, int act) {
    extern __shared__ float sm[];

    int tid  = threadIdx.x;
    int lane = tid & 31, wid = tid >> 5;
    int wr = wid & 3, wc2 = wid >> 2;
    int lr = lane >> 2, lc = lane & 3;
    int m0 = blockIdx.y * 128;
    int n0 = blockIdx.x * 64;

    float acc[2][4][4];
    #pragma unroll
    for (int i = 0; i < 2; ++i)
        #pragma unroll
        for (int j = 0; j < 4; ++j)
            #pragma unroll
            for (int q = 0; q < 4; ++q) acc[i][j][q] = 0.f;

    float4 ra[4], rb[2];
    int a_row[4], a_c4[4], b_row[2], b_c4[2];
    #pragma unroll
    for (int i = 0; i < 4; ++i) { int it = i * 256 + tid; a_row[i] = it >> 3; a_c4[i] = it & 7; }
    #pragma unroll
    for (int i = 0; i < 2; ++i) { int it = i * 256 + tid; b_row[i] = it >> 3; b_c4[i] = it & 7; }

    #define LOAD_G(k0) { \
        _Pragma("unroll") \
        for (int i = 0; i < 4; ++i) \
            ra[i] = *reinterpret_cast<const float4*>(A + (size_t)(m0 + a_row[i]) * FDIM + (k0) + a_c4[i] * 4); \
        _Pragma("unroll") \
        for (int i = 0; i < 2; ++i) \
            rb[i] = (n0 + b_row[i] < Ntot) \
                ? *reinterpret_cast<const float4*>(B + (size_t)(n0 + b_row[i]) * FDIM + (k0) + b_c4[i] * 4) \
                : make_float4(0.f, 0.f, 0.f, 0.f); \
    }
    #define STORE_S(pbuf) { \
        float* Asp = sm + (pbuf) * (ASZ + BSZ); \
        float* Bsp = Asp + ASZ; \
        _Pragma("unroll") \
        for (int i = 0; i < 4; ++i) { \
            float* p = Asp + a_row[i] * SA + a_c4[i] * 4; \
            p[0] = rtf32(ra[i].x); p[1] = rtf32(ra[i].y); p[2] = rtf32(ra[i].z); p[3] = rtf32(ra[i].w); \
        } \
        _Pragma("unroll") \
        for (int i = 0; i < 2; ++i) { \
            float* p = Bsp + b_row[i] * SA + b_c4[i] * 4; \
            p[0] = rtf32(rb[i].x); p[1] = rtf32(rb[i].y); p[2] = rtf32(rb[i].z); p[3] = rtf32(rb[i].w); \
        } \
    }

    LOAD_G(0);
    STORE_S(0);
    __syncthreads();

    #pragma unroll 1
    for (int s = 0; s < 6; ++s) {
        if (s < 5) LOAD_G((s + 1) * 32);

        const float* Asp = sm + (s & 1) * (ASZ + BSZ);
        const float* Bsp = Asp + ASZ;
        #pragma unroll
        for (int ks = 0; ks < 4; ++ks) {
            int kk = ks * 8 + lc;
            uint32_t a[2][4], b[4][2];
            #pragma unroll
            for (int ma = 0; ma < 2; ++ma) {
                int r = wr * 32 + ma * 16 + lr;
                a[ma][0] = __float_as_uint(Asp[r * SA + kk]);
                a[ma][1] = __float_as_uint(Asp[(r + 8) * SA + kk]);
                a[ma][2] = __float_as_uint(Asp[r * SA + kk + 4]);
                a[ma][3] = __float_as_uint(Asp[(r + 8) * SA + kk + 4]);
            }
            #pragma unroll
            for (int na = 0; na < 4; ++na) {
                int bn = wc2 * 32 + na * 8 + lr;
                b[na][0] = __float_as_uint(Bsp[bn * SA + kk]);
                b[na][1] = __float_as_uint(Bsp[bn * SA + kk + 4]);
            }
            #pragma unroll
            for (int ma = 0; ma < 2; ++ma)
                #pragma unroll
                for (int na = 0; na < 4; ++na)
                    mma_tf32(acc[ma][na], a[ma], b[na]);
        }
        if (s < 5) {
            STORE_S((s + 1) & 1);
            __syncthreads();
        }
    }

    // ---- epilogue ----
    #pragma unroll
    for (int ma = 0; ma < 2; ++ma) {
        #pragma unroll
        for (int na = 0; na < 4; ++na) {
            int row = m0 + wr * 32 + ma * 16 + lr;
            int col = n0 + wc2 * 32 + na * 8 + lc * 2;
            #pragma unroll
            for (int half = 0; half < 2; ++half) {
                int r = row + half * 8;
                if (r >= Mstore) continue;
                float v0 = acc[ma][na][half * 2 + 0];
                float v1 = acc[ma][na][half * 2 + 1];
                if (col + 1 < Ntot) {
                    v0 += __ldg(bias + col);
                    v1 += __ldg(bias + col + 1);
                    if (act) { v0 = 1.f / (1.f + expf(-v0)); v1 = 1.f / (1.f + expf(-v1)); }
                    *reinterpret_cast<float2*>(C + (size_t)r * ldc + col) = make_float2(v0, v1);
                } else if (col < Ntot) {
                    v0 += __ldg(bias + col);
                    if (act) v0 = 1.f / (1.f + expf(-v0));
                    C[(size_t)r * ldc + col] = v0;
                }
            }
        }
    }
}

// ================= launch =================
extern "C" void kernel_launch(void* const* d_in, const int* in_sizes, int n_in,
                              void* d_out, int out_size) {
    const int*   prop_ids = (const int*)d_in[0];
    const int*   src      = (const int*)d_in[1];
    const int*   dst      = (const int*)d_in[2];
    const float* embed    = (const float*)d_in[3];
    const float* W_edge   = (const float*)d_in[4];
    const float* W_ih     = (const float*)d_in[5];
    const float* W_hh     = (const float*)d_in[6];
    const float* b_ih     = (const float*)d_in[7];
    const float* b_hh     = (const float*)d_in[8];
    const float* conv_w   = (const float*)d_in[9];
    const float* conv_b   = (const float*)d_in[10];
    float* out = (float*)d_out;

    float *h, *hs, *gi, *gh, *wc;
    cudaGetSymbolAddress((void**)&h,  g_h);
    cudaGetSymbolAddress((void**)&hs, g_hs);
    cudaGetSymbolAddress((void**)&gi, g_gi);
    cudaGetSymbolAddress((void**)&gh, g_gh);
    cudaGetSymbolAddress((void**)&wc, g_wc);

    static int smem_set = 0;
    if (!smem_set) {
        cudaFuncSetAttribute(gemm_mma_kernel,
                             cudaFuncAttributeMaxDynamicSharedMemorySize,
                             SMEM_FLOATS * 4);
        smem_set = 1;
    }

    embed_gather_kernel<<<N_NODES, FDIM>>>(prop_ids, embed);
    fold_kernel<<<F3, FDIM>>>(W_ih, W_edge);

    // ---- CSR build (once per launch) ----
    zero_deg_kernel<<<(NP + 255) / 256, 256>>>();
    csr_count_kernel<<<(N_EDGES + 255) / 256, 256>>>(dst);
    scan_kernel<<<1, 1024>>>();
    csr_fill_kernel<<<(N_EDGES + 255) / 256, 256>>>(src, dst);

    const int MT = NP / 128;                       // 391
    const dim3 grid_576(F3 / 64, MT);              // 9 x 391
    const dim3 grid_100((NCLS2 + 63) / 64, MT);    // 2 x 391
    const int gate_grid = (N_NODES * 48 + 255) / 256;
    const int smem_b = SMEM_FLOATS * 4;

    for (int step = 1; step <= STEP_MAX; ++step) {
        gather_kernel<<<NP / 4, 192>>>();
        gemm_mma_kernel<<<grid_576, 256, smem_b>>>(hs, wc,   b_ih, gi, F3, NP, F3, 0);
        gemm_mma_kernel<<<grid_576, 256, smem_b>>>(h,  W_hh, b_hh, gh, F3, NP, F3, 0);
        gate_kernel<<<gate_grid, 256>>>();
        if (step >= STEP_MIN) {
            int s = step - STEP_MIN;
            gemm_mma_kernel<<<grid_100, 256, smem_b>>>(h, conv_w, conv_b, out + s * NCLS2,
                                                       NCLS2, N_NODES, 5 * NCLS2, 1);
        }
    }
}